// round 7
// baseline (speedup 1.0000x reference)
#include <cuda_runtime.h>
#include <math.h>

// Problem constants (fixed by reference setup_inputs)
#define NB 16
#define NH 1024
#define NW 1024
#define GRID_ELEMS (NB * NH * NW)   // 16777216 floats for odo_grid
#define K_OUT 64                    // 4 * B rows in odo
#define SLOTS 8                     // per-batch key slots

#define NBLOCKS (148 * 6)           // 888 blocks
#define NTHREADS 512

// Cross-block scratch (device globals: allocation-free).
__device__ int g_counter = 0;       // last-block detection; self-resetting
__device__ int g_keys[K_OUT];       // globally ordered keys
__device__ int g_nkeys;             // number of valid keys

// One fused kernel:
//  - block 0 computes the sparse points analytically (inverse affine map in
//    fp32 locates a +/-2 px window; candidates provably lie within +/-1 of
//    the center, exact fp32 reference forward formula decides membership),
//    writes the argwhere tail, and publishes ordered keys to scratch;
//  - all blocks zero the 64MB grid region with float4 stores;
//  - the LAST block to finish scatters the 30.0s (after all zeroing).
__global__ void odo_fused_kernel(const float* __restrict__ rot,
                                 float* __restrict__ out, int out_size) {
    __shared__ int s_bkeys[NB][SLOTS];
    __shared__ int s_cnt[NB];
    __shared__ int s_last;
    int tid = threadIdx.x;
    int bid = blockIdx.x;
    bool tail_ok = (out_size >= GRID_ELEMS + 2 * K_OUT);

    // ---- Phase A: block 0 computes points + tail + scratch keys ----
    if (bid == 0) {
        if (tid < NB) s_cnt[tid] = 0;
        __syncthreads();

        // 16 batches x 5x5 window = 400 threads
        if (tid < NB * 25) {
            int b = tid / 25;
            int j = tid % 25;
            float t00 = rot[b * 6 + 0];  // ca
            float t01 = rot[b * 6 + 1];  // -sa
            float t02 = rot[b * 6 + 2];  // tx
            float t10 = rot[b * 6 + 3];  // sa
            float t11 = rot[b * 6 + 4];  // ca
            float t12 = rot[b * 6 + 5];  // ty

            // Continuous grid coords hitting (ix,iy)=(200,500):
            //   ix = 512*(grid_x+1) - 0.5  =>  grid_x* = 200.5/512 - 1
            const float gxs = 200.5f / 512.0f - 1.0f;
            const float gys = 500.5f / 512.0f - 1.0f;
            float rx = gxs - t02;
            float ry = gys - t12;
            // Rotation (det=1): inverse = transpose.
            float gx0 = t00 * rx + t10 * ry;
            float gy0 = t01 * rx + t11 * ry;
            float w0 = 512.0f * (gx0 + 1.0f) - 0.5f;
            float h0 = 512.0f * (gy0 + 1.0f) - 0.5f;

            int wc = (int)floorf(w0 + 0.5f) + (j % 5) - 2;
            int hc = (int)floorf(h0 + 0.5f) + (j / 5) - 2;

            if (wc >= 0 && wc < NW && hc >= 0 && hc < NH) {
                // Exact float32 forward evaluation (reference formula).
                float gx = (2.0f * (float)wc + 1.0f) / 1024.0f - 1.0f;
                float gy = (2.0f * (float)hc + 1.0f) / 1024.0f - 1.0f;
                float grid_x = t00 * gx + t01 * gy + t02;
                float grid_y = t10 * gx + t11 * gy + t12;
                float ix = ((grid_x + 1.0f) * 1024.0f - 1.0f) * 0.5f;
                float iy = ((grid_y + 1.0f) * 1024.0f - 1.0f) * 0.5f;
                // jnp.round = round-half-to-even = rintf (RN mode)
                float rxf = rintf(ix);
                float ryf = rintf(iy);
                rxf = fminf(fmaxf(rxf, 0.0f), (float)(NW - 1));
                ryf = fminf(fmaxf(ryf, 0.0f), (float)(NH - 1));
                if (rxf == 200.0f && ryf == 500.0f) {
                    int key = (b * NH + hc) * NW + wc;  // row-major index
                    int slot = atomicAdd(&s_cnt[b], 1);
                    if (slot < SLOTS) s_bkeys[b][slot] = key;
                }
            }
        }
        __syncthreads();

        float* odo = out + GRID_ELEMS;
        // Parallel -1 fill of the odo tail (128 floats).
        if (tail_ok && tid < 2 * K_OUT) odo[tid] = -1.0f;
        __syncthreads();

        // One thread per batch: exclusive offset, register sort of <=SLOTS
        // keys, write (h,w) pairs + ordered keys to device scratch.
        // (key = b*HW + h*W + w is monotone in b, so batch-ordered output
        // with per-batch sorted keys IS the global argwhere order.)
        if (tid < NB) {
            int off = 0;
            int total = 0;
            #pragma unroll
            for (int i = 0; i < NB; i++) {
                int c = s_cnt[i];
                if (c > SLOTS) c = SLOTS;
                if (i < tid) off += c;
                total += c;
            }
            int n = s_cnt[tid];
            if (n > SLOTS) n = SLOTS;
            int keys[SLOTS];
            #pragma unroll
            for (int i = 0; i < SLOTS; i++)
                keys[i] = (i < n) ? s_bkeys[tid][i] : 0x7FFFFFFF;
            // Small register insertion sort.
            #pragma unroll
            for (int i = 1; i < SLOTS; i++) {
                int k = keys[i];
                int p = i - 1;
                #pragma unroll
                for (int q = SLOTS - 2; q >= 0; q--) {
                    if (q == p && p >= 0 && keys[p] > k) {
                        keys[p + 1] = keys[p];
                        p--;
                    }
                }
                keys[p + 1] = k;
            }
            for (int i = 0; i < n; i++) {
                int pos = off + i;
                if (pos < K_OUT) {
                    int key = keys[i];
                    g_keys[pos] = key;
                    if (tail_ok) {
                        odo[2 * pos + 0] = (float)((key >> 10) & (NH - 1));
                        odo[2 * pos + 1] = (float)(key & (NW - 1));
                    }
                }
            }
            if (tid == 0) g_nkeys = (total > K_OUT) ? K_OUT : total;
        }
        // Visibility of g_keys/g_nkeys to the scatter block is established
        // by this block's threadfence + atomic arrival below; the scatter
        // proceeds only after ALL blocks (incl. this one) have arrived.
    }

    // ---- Phase B: all blocks zero the grid region (float4 stores) ----
    {
        float4* out4 = (float4*)out;
        const float4 z = make_float4(0.f, 0.f, 0.f, 0.f);
        const int n4 = GRID_ELEMS >> 2;
        for (int i = bid * NTHREADS + tid; i < n4; i += NBLOCKS * NTHREADS) {
            out4[i] = z;
        }
    }

    // ---- Phase C: last-block scatter of the sparse 30.0s ----
    __threadfence();      // order this thread's stores before the arrival
    __syncthreads();      // all threads of this block have fenced
    if (tid == 0) {
        int old = atomicAdd(&g_counter, 1);
        s_last = (old == NBLOCKS - 1) ? 1 : 0;
    }
    __syncthreads();
    if (s_last) {
        __threadfence();  // acquire side: see all blocks' zero stores + keys
        int nk = g_nkeys;
        if (tid < nk) out[g_keys[tid]] = 30.0f;
        if (tid == 0) g_counter = 0;  // self-reset for next graph replay
    }
}

extern "C" void kernel_launch(void* const* d_in, const int* in_sizes, int n_in,
                              void* d_out, int out_size) {
    // Inputs per metadata order: d_in[0]=cost_map_batch (unused by the math),
    // d_in[1]=rot_mat (16x2x3 float32).
    const float* rot = (const float*)d_in[1];
    float* out = (float*)d_out;
    odo_fused_kernel<<<NBLOCKS, NTHREADS, 0, 0>>>(rot, out, out_size);
}

// round 8
// speedup vs baseline: 1.0230x; 1.0230x over previous
#include <cuda_runtime.h>
#include <math.h>

// Problem constants (fixed by reference setup_inputs)
#define NB 16
#define NH 1024
#define NW 1024
#define GRID_ELEMS (NB * NH * NW)   // 16777216 floats for odo_grid
#define K_OUT 64                    // 4 * B rows in odo
#define SLOTS 8                     // per-batch key slots (provably <=4 match)

#define NBLOCKS (148 * 12)          // 1776 blocks (proven-fast fill geometry)
#define NTHREADS 256
#define TOT (NBLOCKS * NTHREADS)    // 454656 threads

// Fully fused, zero cross-block sync:
//  - EVERY block redundantly computes the <=64 sparse keys (3x3 window per
//    batch around the fp32-inverted center; any true match is provably
//    within integer offset +/-1), publishing keys + owner-thread ids to
//    shared memory;
//  - all blocks zero the 64MB grid with float4 stores;
//  - each thread then re-stores 30.0f to the keys whose float4 chunk it
//    owns — same-thread same-address program order makes this safe with
//    NO fences/atomics;
//  - block 0 writes the argwhere tail (-1 fill, then (h,w) pairs).
__global__ void __launch_bounds__(NTHREADS, 8)
odo_fused_kernel(const float* __restrict__ rot,
                 float* __restrict__ out, int out_size) {
    __shared__ int s_bkeys[NB][SLOTS];
    __shared__ int s_cnt[NB];
    __shared__ int s_keys[K_OUT];   // globally ordered keys
    __shared__ int s_owner[K_OUT];  // owning global thread id per key
    __shared__ int s_nk;
    int tid = threadIdx.x;
    int bid = blockIdx.x;
    int gtid = bid * NTHREADS + tid;
    bool tail_ok = (out_size >= GRID_ELEMS + 2 * K_OUT);
    float* odo = out + GRID_ELEMS;

    // Phase 1: init counts; block 0 also -1 fills the odo tail (128 floats).
    if (tid < NB) s_cnt[tid] = 0;
    if (bid == 0 && tail_ok && tid < 2 * K_OUT) odo[tid] = -1.0f;
    __syncthreads();

    // Phase 2: candidates. 16 batches x 3x3 window = 144 threads.
    if (tid < NB * 9) {
        int b = tid / 9;
        int j = tid % 9;
        float t00 = rot[b * 6 + 0];  // ca
        float t01 = rot[b * 6 + 1];  // -sa
        float t02 = rot[b * 6 + 2];  // tx
        float t10 = rot[b * 6 + 3];  // sa
        float t11 = rot[b * 6 + 4];  // ca
        float t12 = rot[b * 6 + 5];  // ty

        // Continuous grid coords hitting (ix,iy)=(200,500):
        //   ix = 512*(grid_x+1) - 0.5  =>  grid_x* = 200.5/512 - 1
        const float gxs = 200.5f / 512.0f - 1.0f;
        const float gys = 500.5f / 512.0f - 1.0f;
        float rx = gxs - t02;
        float ry = gys - t12;
        // Rotation (det=1): inverse = transpose.
        float gx0 = t00 * rx + t10 * ry;
        float gy0 = t01 * rx + t11 * ry;
        float w0 = 512.0f * (gx0 + 1.0f) - 0.5f;
        float h0 = 512.0f * (gy0 + 1.0f) - 0.5f;

        // Any lattice point mapping into the target unit square lies within
        // 0.5*sqrt(2)~0.708px of (w0,h0); |int - round(center)| <= 1.
        int wc = (int)floorf(w0 + 0.5f) + (j % 3) - 1;
        int hc = (int)floorf(h0 + 0.5f) + (j / 3) - 1;

        if (wc >= 0 && wc < NW && hc >= 0 && hc < NH) {
            // Exact float32 forward evaluation (reference formula).
            float gx = (2.0f * (float)wc + 1.0f) / 1024.0f - 1.0f;
            float gy = (2.0f * (float)hc + 1.0f) / 1024.0f - 1.0f;
            float grid_x = t00 * gx + t01 * gy + t02;
            float grid_y = t10 * gx + t11 * gy + t12;
            float ix = ((grid_x + 1.0f) * 1024.0f - 1.0f) * 0.5f;
            float iy = ((grid_y + 1.0f) * 1024.0f - 1.0f) * 0.5f;
            // jnp.round = round-half-to-even = rintf (RN mode)
            float rxf = rintf(ix);
            float ryf = rintf(iy);
            rxf = fminf(fmaxf(rxf, 0.0f), (float)(NW - 1));
            ryf = fminf(fmaxf(ryf, 0.0f), (float)(NH - 1));
            if (rxf == 200.0f && ryf == 500.0f) {
                int key = (b * NH + hc) * NW + wc;  // row-major index
                int slot = atomicAdd(&s_cnt[b], 1);
                if (slot < SLOTS) s_bkeys[b][slot] = key;
            }
        }
    }
    __syncthreads();

    // Phase 3: one thread per batch sorts its keys and emits ordered keys +
    // owner ids. (key = b*HW + h*W + w is monotone in b, so batch-ordered
    // output with per-batch sorted keys IS the global argwhere order.)
    if (tid < NB) {
        int off = 0;
        int total = 0;
        #pragma unroll
        for (int i = 0; i < NB; i++) {
            int c = s_cnt[i];
            if (c > SLOTS) c = SLOTS;
            if (i < tid) off += c;
            total += c;
        }
        int n = s_cnt[tid];
        if (n > SLOTS) n = SLOTS;
        int keys[SLOTS];
        #pragma unroll
        for (int i = 0; i < SLOTS; i++)
            keys[i] = (i < n) ? s_bkeys[tid][i] : 0x7FFFFFFF;
        // Small register insertion sort.
        #pragma unroll
        for (int i = 1; i < SLOTS; i++) {
            int k = keys[i];
            int p = i - 1;
            #pragma unroll
            for (int q = SLOTS - 2; q >= 0; q--) {
                if (q == p && p >= 0 && keys[p] > k) {
                    keys[p + 1] = keys[p];
                    p--;
                }
            }
            keys[p + 1] = k;
        }
        for (int i = 0; i < n; i++) {
            int pos = off + i;
            if (pos < K_OUT) {
                int key = keys[i];
                s_keys[pos] = key;
                s_owner[pos] = (key >> 2) % TOT;  // thread owning chunk key>>2
                if (bid == 0 && tail_ok) {
                    odo[2 * pos + 0] = (float)((key >> 10) & (NH - 1));
                    odo[2 * pos + 1] = (float)(key & (NW - 1));
                }
            }
        }
        if (tid == 0) s_nk = (total > K_OUT) ? K_OUT : total;
    }
    __syncthreads();

    // Phase 4: zero the grid region (float4 stores, grid-stride).
    {
        float4* out4 = (float4*)out;
        const float4 z = make_float4(0.f, 0.f, 0.f, 0.f);
        const int n4 = GRID_ELEMS >> 2;
        for (int i = gtid; i < n4; i += TOT) {
            out4[i] = z;
        }
    }

    // Phase 5: thread-local patch. The owning thread re-stores 30.0f over
    // its own earlier zero store — same thread, same address, program order.
    {
        int nk = s_nk;
        for (int i = 0; i < nk; i++) {
            if (s_owner[i] == gtid) out[s_keys[i]] = 30.0f;
        }
    }
}

extern "C" void kernel_launch(void* const* d_in, const int* in_sizes, int n_in,
                              void* d_out, int out_size) {
    // Inputs per metadata order: d_in[0]=cost_map_batch (unused by the math),
    // d_in[1]=rot_mat (16x2x3 float32).
    const float* rot = (const float*)d_in[1];
    float* out = (float*)d_out;
    odo_fused_kernel<<<NBLOCKS, NTHREADS, 0, 0>>>(rot, out, out_size);
}

// round 9
// speedup vs baseline: 1.0409x; 1.0175x over previous
#include <cuda_runtime.h>
#include <math.h>

// Problem constants (fixed by reference setup_inputs)
#define NB 16
#define NH 1024
#define NW 1024
#define GRID_ELEMS (NB * NH * NW)   // 16777216 floats for odo_grid
#define K_OUT 64                    // 4 * B rows in odo
#define SLOTS 8                     // per-batch key slots (provably <=4 match)

#define NBLOCKS (148 * 12)          // 1776 blocks (proven-fast fill geometry)
#define NTHREADS 256
#define TOT (NBLOCKS * NTHREADS)    // 454656 threads

// Fully fused, zero cross-block sync, stores-first ordering:
//  - every thread starts the 64MB float4 zero loop IMMEDIATELY (no prologue
//    before the first store);
//  - afterwards each block redundantly computes the <=64 sparse keys (3x3
//    window per batch around the fp32-inverted center; any true match is
//    provably within integer offset +/-1) — this latency overlaps other
//    blocks' store traffic and this block's store drain;
//  - each thread then re-stores 30.0f to the keys whose float4 chunk it
//    owns (same thread, same address, program order — no fences needed);
//  - block 0 writes the argwhere tail.
__global__ void __launch_bounds__(NTHREADS, 8)
odo_fused_kernel(const float* __restrict__ rot,
                 float* __restrict__ out, int out_size) {
    __shared__ int s_bkeys[NB][SLOTS];
    __shared__ int s_cnt[NB];
    __shared__ int s_keys[K_OUT];   // globally ordered keys
    __shared__ int s_owner[K_OUT];  // owning global thread id per key
    __shared__ int s_nk;
    int tid = threadIdx.x;
    int bid = blockIdx.x;
    int gtid = bid * NTHREADS + tid;
    bool tail_ok = (out_size >= GRID_ELEMS + 2 * K_OUT);
    float* odo = out + GRID_ELEMS;

    if (tid < NB) s_cnt[tid] = 0;

    // ---- Phase 1: zero the grid region FIRST (float4 grid-stride) ----
    {
        float4* out4 = (float4*)out;
        const float4 z = make_float4(0.f, 0.f, 0.f, 0.f);
        const int n4 = GRID_ELEMS >> 2;
        for (int i = gtid; i < n4; i += TOT) {
            out4[i] = z;
        }
    }
    __syncthreads();  // s_cnt init visible; block store phase complete

    // ---- Phase 2: candidates. 16 batches x 3x3 window = 144 threads ----
    if (tid < NB * 9) {
        int b = tid / 9;
        int j = tid % 9;
        float t00 = rot[b * 6 + 0];  // ca
        float t01 = rot[b * 6 + 1];  // -sa
        float t02 = rot[b * 6 + 2];  // tx
        float t10 = rot[b * 6 + 3];  // sa
        float t11 = rot[b * 6 + 4];  // ca
        float t12 = rot[b * 6 + 5];  // ty

        // Continuous grid coords hitting (ix,iy)=(200,500):
        //   ix = 512*(grid_x+1) - 0.5  =>  grid_x* = 200.5/512 - 1
        const float gxs = 200.5f / 512.0f - 1.0f;
        const float gys = 500.5f / 512.0f - 1.0f;
        float rx = gxs - t02;
        float ry = gys - t12;
        // Rotation (det=1): inverse = transpose.
        float gx0 = t00 * rx + t10 * ry;
        float gy0 = t01 * rx + t11 * ry;
        float w0 = 512.0f * (gx0 + 1.0f) - 0.5f;
        float h0 = 512.0f * (gy0 + 1.0f) - 0.5f;

        // Any lattice point mapping into the target unit square lies within
        // 0.5*sqrt(2)~0.708px of (w0,h0); |int - round(center)| <= 1.
        int wc = (int)floorf(w0 + 0.5f) + (j % 3) - 1;
        int hc = (int)floorf(h0 + 0.5f) + (j / 3) - 1;

        if (wc >= 0 && wc < NW && hc >= 0 && hc < NH) {
            // Exact float32 forward evaluation (reference formula).
            float gx = (2.0f * (float)wc + 1.0f) / 1024.0f - 1.0f;
            float gy = (2.0f * (float)hc + 1.0f) / 1024.0f - 1.0f;
            float grid_x = t00 * gx + t01 * gy + t02;
            float grid_y = t10 * gx + t11 * gy + t12;
            float ix = ((grid_x + 1.0f) * 1024.0f - 1.0f) * 0.5f;
            float iy = ((grid_y + 1.0f) * 1024.0f - 1.0f) * 0.5f;
            // jnp.round = round-half-to-even = rintf (RN mode)
            float rxf = rintf(ix);
            float ryf = rintf(iy);
            rxf = fminf(fmaxf(rxf, 0.0f), (float)(NW - 1));
            ryf = fminf(fmaxf(ryf, 0.0f), (float)(NH - 1));
            if (rxf == 200.0f && ryf == 500.0f) {
                int key = (b * NH + hc) * NW + wc;  // row-major index
                int slot = atomicAdd(&s_cnt[b], 1);
                if (slot < SLOTS) s_bkeys[b][slot] = key;
            }
        }
    }
    __syncthreads();

    // ---- Phase 3: per-batch sort, ordered keys + owners, tail (block 0) ----
    // (key = b*HW + h*W + w is monotone in b, so batch-ordered output with
    // per-batch sorted keys IS the global argwhere order.)
    if (tid < NB) {
        int off = 0;
        int total = 0;
        #pragma unroll
        for (int i = 0; i < NB; i++) {
            int c = s_cnt[i];
            if (c > SLOTS) c = SLOTS;
            if (i < tid) off += c;
            total += c;
        }
        int n = s_cnt[tid];
        if (n > SLOTS) n = SLOTS;
        int keys[SLOTS];
        #pragma unroll
        for (int i = 0; i < SLOTS; i++)
            keys[i] = (i < n) ? s_bkeys[tid][i] : 0x7FFFFFFF;
        // Small register insertion sort.
        #pragma unroll
        for (int i = 1; i < SLOTS; i++) {
            int k = keys[i];
            int p = i - 1;
            #pragma unroll
            for (int q = SLOTS - 2; q >= 0; q--) {
                if (q == p && p >= 0 && keys[p] > k) {
                    keys[p + 1] = keys[p];
                    p--;
                }
            }
            keys[p + 1] = k;
        }
        for (int i = 0; i < n; i++) {
            int pos = off + i;
            if (pos < K_OUT) {
                int key = keys[i];
                s_keys[pos] = key;
                s_owner[pos] = (key >> 2) % TOT;  // thread owning chunk key>>2
                if (bid == 0 && tail_ok) {
                    odo[2 * pos + 0] = (float)((key >> 10) & (NH - 1));
                    odo[2 * pos + 1] = (float)(key & (NW - 1));
                }
            }
        }
        if (tid == 0) s_nk = (total > K_OUT) ? K_OUT : total;
    }
    // Block 0: -1 fill of the remaining odo tail slots (parallel, disjoint
    // from the pair writes above only when pos>=nk; do it via tid>=... safe
    // approach: fill all 128 with -1 BEFORE pair writes is impossible now,
    // so fill only slots >= total pairs).
    __syncthreads();
    if (bid == 0 && tail_ok) {
        int nk = s_nk;
        int i = tid;  // 0..2*K_OUT-1 handled by first 128 threads
        if (i < 2 * K_OUT && (i >> 1) >= nk) odo[i] = -1.0f;
    }

    // ---- Phase 4: thread-local patch (program-ordered same-thread store) --
    {
        int nk = s_nk;
        for (int i = 0; i < nk; i++) {
            if (s_owner[i] == gtid) out[s_keys[i]] = 30.0f;
        }
    }
}

extern "C" void kernel_launch(void* const* d_in, const int* in_sizes, int n_in,
                              void* d_out, int out_size) {
    // Inputs per metadata order: d_in[0]=cost_map_batch (unused by the math),
    // d_in[1]=rot_mat (16x2x3 float32).
    const float* rot = (const float*)d_in[1];
    float* out = (float*)d_out;
    odo_fused_kernel<<<NBLOCKS, NTHREADS, 0, 0>>>(rot, out, out_size);
}

// round 10
// speedup vs baseline: 1.0430x; 1.0020x over previous
#include <cuda_runtime.h>
#include <math.h>

// Problem constants (fixed by reference setup_inputs)
#define NB 16
#define NH 1024
#define NW 1024
#define GRID_ELEMS (NB * NH * NW)   // 16777216 floats for odo_grid
#define K_OUT 64                    // 4 * B rows in odo

// ---------------------------------------------------------------------------
// Kernel 1: proven zero-fill (identical to the 10.3us R4 kernel).
// Covers ALL out_size floats (grid + tail); the point kernel then overwrites
// the tail completely (pairs + -1s) and patches the sparse 30.0s.
// ---------------------------------------------------------------------------
__global__ void zero_fill_kernel(float* __restrict__ out, int n) {
    int n4 = n >> 2;  // number of full float4 chunks
    float4* out4 = (float4*)out;
    const float4 z = make_float4(0.f, 0.f, 0.f, 0.f);
    for (int i = blockIdx.x * blockDim.x + threadIdx.x; i < n4;
         i += gridDim.x * blockDim.x) {
        out4[i] = z;
    }
    int tail = n & 3;
    int gtid = blockIdx.x * blockDim.x + threadIdx.x;
    if (gtid < tail) out[n4 * 4 + gtid] = 0.f;
}

// ---------------------------------------------------------------------------
// Kernel 2: SINGLE WARP, no barriers, no shared memory, no sort.
// Lane b (<16) owns batch b: fp32 inverse affine map locates the candidate
// center (any true match is provably within integer offset +/-1: a lattice
// point mapping into the target unit square lies within 0.5*sqrt(2)=0.708px
// of the continuous preimage center). The lane scans the 3x3 window
// SERIALLY in (h outer, w inner) order, so collected keys are already in
// increasing row-major order — argwhere order for free. Warp prefix sum
// gives global offsets (key = b*HW + h*W + w is monotone in b).
// Runs after the fill on the same stream, so its stores win.
// ---------------------------------------------------------------------------
__global__ void odo_points_warp(const float* __restrict__ rot,
                                float* __restrict__ out, int out_size) {
    const unsigned mask = 0xFFFFFFFFu;
    int lane = threadIdx.x;

    int cnt = 0;
    int keys[6];

    if (lane < NB) {
        int b = lane;
        float t00 = rot[b * 6 + 0];  // ca
        float t01 = rot[b * 6 + 1];  // -sa
        float t02 = rot[b * 6 + 2];  // tx
        float t10 = rot[b * 6 + 3];  // sa
        float t11 = rot[b * 6 + 4];  // ca
        float t12 = rot[b * 6 + 5];  // ty

        // Continuous grid coords hitting (ix,iy)=(200,500):
        //   ix = 512*(grid_x+1) - 0.5  =>  grid_x* = 200.5/512 - 1
        const float gxs = 200.5f / 512.0f - 1.0f;
        const float gys = 500.5f / 512.0f - 1.0f;
        float rx = gxs - t02;
        float ry = gys - t12;
        // Rotation (det=1): inverse = transpose.
        float gx0 = t00 * rx + t10 * ry;
        float gy0 = t01 * rx + t11 * ry;
        float w0 = 512.0f * (gx0 + 1.0f) - 0.5f;
        float h0 = 512.0f * (gy0 + 1.0f) - 0.5f;

        int wr = (int)floorf(w0 + 0.5f);
        int hr = (int)floorf(h0 + 0.5f);

        // Serial 3x3 scan, h outer / w inner => keys collected in
        // increasing row-major order (pre-sorted).
        #pragma unroll
        for (int dh = -1; dh <= 1; dh++) {
            #pragma unroll
            for (int dw = -1; dw <= 1; dw++) {
                int hc = hr + dh;
                int wc = wr + dw;
                if (wc >= 0 && wc < NW && hc >= 0 && hc < NH) {
                    // Exact float32 forward evaluation (reference formula).
                    float gx = (2.0f * (float)wc + 1.0f) / 1024.0f - 1.0f;
                    float gy = (2.0f * (float)hc + 1.0f) / 1024.0f - 1.0f;
                    float grid_x = t00 * gx + t01 * gy + t02;
                    float grid_y = t10 * gx + t11 * gy + t12;
                    float ix = ((grid_x + 1.0f) * 1024.0f - 1.0f) * 0.5f;
                    float iy = ((grid_y + 1.0f) * 1024.0f - 1.0f) * 0.5f;
                    // jnp.round = round-half-to-even = rintf (RN mode)
                    float rxf = rintf(ix);
                    float ryf = rintf(iy);
                    rxf = fminf(fmaxf(rxf, 0.0f), (float)(NW - 1));
                    ryf = fminf(fmaxf(ryf, 0.0f), (float)(NH - 1));
                    if (rxf == 200.0f && ryf == 500.0f && cnt < 6) {
                        keys[cnt++] = (b * NH + hc) * NW + wc;
                    }
                }
            }
        }
    }

    // Warp-inclusive prefix sum over per-lane counts (lanes >=16 hold 0).
    int inc = cnt;
    #pragma unroll
    for (int d = 1; d < 32; d <<= 1) {
        int v = __shfl_up_sync(mask, inc, d);
        if (lane >= d) inc += v;
    }
    int off = inc - cnt;                    // exclusive prefix
    int total = __shfl_sync(mask, inc, 31); // grand total
    if (total > K_OUT) total = K_OUT;

    bool tail_ok = (out_size >= GRID_ELEMS + 2 * K_OUT);
    float* odo = out + GRID_ELEMS;

    // Sparse 30.0s (always, all matches) + argwhere pairs (first K_OUT).
    for (int i = 0; i < cnt; i++) {
        int key = keys[i];
        out[key] = 30.0f;
        int pos = off + i;
        if (tail_ok && pos < K_OUT) {
            odo[2 * pos + 0] = (float)((key >> 10) & (NH - 1));
            odo[2 * pos + 1] = (float)(key & (NW - 1));
        }
    }

    // -1 fill of the remaining tail slots (disjoint from pair writes).
    if (tail_ok) {
        for (int i = 2 * total + lane; i < 2 * K_OUT; i += 32) {
            odo[i] = -1.0f;
        }
    }
}

extern "C" void kernel_launch(void* const* d_in, const int* in_sizes, int n_in,
                              void* d_out, int out_size) {
    // Inputs per metadata order: d_in[0]=cost_map_batch (unused by the math),
    // d_in[1]=rot_mat (16x2x3 float32).
    const float* rot = (const float*)d_in[1];
    float* out = (float*)d_out;

    // Zero everything (proven-fastest geometry), then patch with one warp.
    zero_fill_kernel<<<148 * 12, 256, 0, 0>>>(out, out_size);
    odo_points_warp<<<1, 32, 0, 0>>>(rot, out, out_size);
}

// round 11
// speedup vs baseline: 1.1172x; 1.0711x over previous
#include <cuda_runtime.h>
#include <math.h>

// Problem constants (fixed by reference setup_inputs)
#define NB 16
#define NH 1024
#define NW 1024
#define GRID_ELEMS (NB * NH * NW)   // 16777216 floats for odo_grid
#define K_OUT 64                    // 4 * B rows in odo

#define NBLOCKS (148 * 12)          // 1776 blocks (proven fill geometry)
#define NTHREADS 256
#define TOT (NBLOCKS * NTHREADS)    // 454656 threads

// Single fused kernel, one launch overhead, near-zero patch cost:
//  - warp 0 of every block runs the single-warp point logic (lane b inverts
//    batch b's affine map in fp32; any true match is provably within +/-1 of
//    the rounded center since a lattice point mapping into the target unit
//    square lies within 0.708px of the continuous preimage; serial 3x3 scan
//    in h-outer/w-inner order yields PRE-SORTED keys; shfl prefix sum gives
//    argwhere offsets). Block 0's warp 0 also writes the whole odo tail.
//  - all warps zero the grid region (float4 grid-stride; tail excluded).
//  - __syncthreads (block-scope fence), then warp 0 re-stores 30.0f for the
//    keys whose zeroing thread lives in THIS block — same-block same-address
//    stores separated by a barrier are coherently ordered. ~15 instructions
//    per block, vs the 64-iter all-thread scan that cost ~3us in R8/R9.
__global__ void __launch_bounds__(NTHREADS, 8)
odo_fused_kernel(const float* __restrict__ rot,
                 float* __restrict__ out, int out_size) {
    __shared__ int s_keys[K_OUT];
    __shared__ int s_nk;
    const unsigned fullmask = 0xFFFFFFFFu;
    int tid = threadIdx.x;
    int bid = blockIdx.x;
    int gtid = bid * NTHREADS + tid;
    bool tail_ok = (out_size >= GRID_ELEMS + 2 * K_OUT);

    // ---- Phase A: warp 0 computes the sparse keys ----
    if (tid < 32) {
        int lane = tid;
        int cnt = 0;
        int keys[6];

        if (lane < NB) {
            int b = lane;
            float t00 = rot[b * 6 + 0];  // ca
            float t01 = rot[b * 6 + 1];  // -sa
            float t02 = rot[b * 6 + 2];  // tx
            float t10 = rot[b * 6 + 3];  // sa
            float t11 = rot[b * 6 + 4];  // ca
            float t12 = rot[b * 6 + 5];  // ty

            // Continuous grid coords hitting (ix,iy)=(200,500):
            //   ix = 512*(grid_x+1) - 0.5  =>  grid_x* = 200.5/512 - 1
            const float gxs = 200.5f / 512.0f - 1.0f;
            const float gys = 500.5f / 512.0f - 1.0f;
            float rx = gxs - t02;
            float ry = gys - t12;
            // Rotation (det=1): inverse = transpose.
            float gx0 = t00 * rx + t10 * ry;
            float gy0 = t01 * rx + t11 * ry;
            float w0 = 512.0f * (gx0 + 1.0f) - 0.5f;
            float h0 = 512.0f * (gy0 + 1.0f) - 0.5f;

            int wr = (int)floorf(w0 + 0.5f);
            int hr = (int)floorf(h0 + 0.5f);

            // Serial 3x3 scan, h outer / w inner => keys pre-sorted.
            #pragma unroll
            for (int dh = -1; dh <= 1; dh++) {
                #pragma unroll
                for (int dw = -1; dw <= 1; dw++) {
                    int hc = hr + dh;
                    int wc = wr + dw;
                    if (wc >= 0 && wc < NW && hc >= 0 && hc < NH) {
                        // Exact float32 forward eval (reference formula).
                        float gx = (2.0f * (float)wc + 1.0f) / 1024.0f - 1.0f;
                        float gy = (2.0f * (float)hc + 1.0f) / 1024.0f - 1.0f;
                        float grid_x = t00 * gx + t01 * gy + t02;
                        float grid_y = t10 * gx + t11 * gy + t12;
                        float ixf = ((grid_x + 1.0f) * 1024.0f - 1.0f) * 0.5f;
                        float iyf = ((grid_y + 1.0f) * 1024.0f - 1.0f) * 0.5f;
                        // jnp.round = round-half-to-even = rintf (RN mode)
                        float rxf = rintf(ixf);
                        float ryf = rintf(iyf);
                        rxf = fminf(fmaxf(rxf, 0.0f), (float)(NW - 1));
                        ryf = fminf(fmaxf(ryf, 0.0f), (float)(NH - 1));
                        if (rxf == 200.0f && ryf == 500.0f && cnt < 6) {
                            keys[cnt++] = (b * NH + hc) * NW + wc;
                        }
                    }
                }
            }
        }

        // Warp-inclusive prefix sum over per-lane counts.
        int inc = cnt;
        #pragma unroll
        for (int d = 1; d < 32; d <<= 1) {
            int v = __shfl_up_sync(fullmask, inc, d);
            if (lane >= d) inc += v;
        }
        int off = inc - cnt;                        // exclusive prefix
        int total = __shfl_sync(fullmask, inc, 31); // grand total
        if (total > K_OUT) total = K_OUT;
        if (lane == 0) s_nk = total;

        // Publish ordered keys (key = b*HW+h*W+w monotone in b => batch
        // order + per-batch sorted = global argwhere order).
        for (int i = 0; i < cnt; i++) {
            int pos = off + i;
            if (pos < K_OUT) s_keys[pos] = keys[i];
        }

        // Block 0: write the entire odo tail (pairs + -1 fill). The zero
        // loop below never touches the tail region, so no race.
        if (bid == 0 && tail_ok) {
            float* odo = out + GRID_ELEMS;
            for (int i = 0; i < cnt; i++) {
                int pos = off + i;
                if (pos < K_OUT) {
                    int key = keys[i];
                    odo[2 * pos + 0] = (float)((key >> 10) & (NH - 1));
                    odo[2 * pos + 1] = (float)(key & (NW - 1));
                }
            }
            int tail_floats = out_size - GRID_ELEMS;
            for (int i = 2 * total + lane; i < tail_floats; i += 32) {
                odo[i] = -1.0f;
            }
        }
    }

    // ---- Phase B: zero the grid region (float4 grid-stride) ----
    {
        float4* out4 = (float4*)out;
        const float4 z = make_float4(0.f, 0.f, 0.f, 0.f);
        const int n4 = GRID_ELEMS >> 2;
        for (int i = gtid; i < n4; i += TOT) {
            out4[i] = z;
        }
    }

    // Block-scope barrier + fence: orders this block's zero-stores before
    // the patch stores below (same block, same address => coherent).
    __syncthreads();

    // ---- Phase C: warp 0 patches keys owned by THIS block ----
    if (tid < 32) {
        int nk = s_nk;
        #pragma unroll
        for (int r = 0; r < 2; r++) {
            int idx = tid + 32 * r;
            if (idx < nk) {
                int key = s_keys[idx];
                int owner_thread = (key >> 2) % TOT;  // thread that zeroed it
                if ((owner_thread >> 8) == bid) {     // /NTHREADS
                    out[key] = 30.0f;
                }
            }
        }
    }
}

extern "C" void kernel_launch(void* const* d_in, const int* in_sizes, int n_in,
                              void* d_out, int out_size) {
    // Inputs per metadata order: d_in[0]=cost_map_batch (unused by the math),
    // d_in[1]=rot_mat (16x2x3 float32).
    const float* rot = (const float*)d_in[1];
    float* out = (float*)d_out;
    odo_fused_kernel<<<NBLOCKS, NTHREADS, 0, 0>>>(rot, out, out_size);
}